// round 1
// baseline (speedup 1.0000x reference)
#include <cuda_runtime.h>
#include <cstdint>
#include <cstddef>

#define T_STEPS 512
#define BATCH   64
#define HID     512
#define INP     512
#define G4      2048            // 4*HID
#define HPAD    516             // padded row stride (floats) to break bank conflicts
#define NBLK    128             // persistent grid size

// ---------------- device scratch (static; no runtime allocation) ----------------
__device__ float g_xg[(size_t)T_STEPS * BATCH * G4];   // [T][B][4H]  (256 MB)
__device__ float g_hbuf[2][BATCH * HID];               // ping-pong h
__device__ unsigned int g_bar;                         // grid barrier counter

// ---------------- f32x2 helpers ----------------
__device__ __forceinline__ void ffma2(unsigned long long &c, unsigned long long a,
                                      unsigned long long b) {
    asm("fma.rn.f32x2 %0, %1, %2, %0;" : "+l"(c) : "l"(a), "l"(b));
}
__device__ __forceinline__ float hsum2(unsigned long long v) {
    float lo, hi;
    asm("mov.b64 {%0, %1}, %2;" : "=f"(lo), "=f"(hi) : "l"(v));
    return lo + hi;
}

// =================================================================================
// Kernel 1: xg[t][b][g] = x[b,t,:] . W_ih[g,:] + (b_ih[g] + b_hh[g])
// GEMM M=32768 (m = b*512+t), N=2048, K=512.  Tile 128x64, 256 threads, thread 8x4.
// f32x2 accumulation over k pairs.
// =================================================================================
__global__ __launch_bounds__(256) void xg_gemm_kernel(
        const float* __restrict__ x, const float* __restrict__ Wih,
        const float* __restrict__ bih, const float* __restrict__ bhh) {
    __shared__ __align__(16) float2 As2[8][128];   // [k_pair][m]
    __shared__ __align__(16) float2 Bs2[8][64];    // [k_pair][n]

    const int tid = threadIdx.x;
    const int tx = tid & 15;        // n-dim thread coord (0..15)
    const int ty = tid >> 4;        // m-dim thread coord (0..15)
    const int m0 = blockIdx.y * 128;
    const int n0 = blockIdx.x * 64;

    unsigned long long acc[8][4];
    #pragma unroll
    for (int i = 0; i < 8; ++i)
        #pragma unroll
        for (int j = 0; j < 4; ++j) acc[i][j] = 0ull;

    for (int k0 = 0; k0 < INP; k0 += 16) {
        // load A tile: 128 rows x 16 k  (512 float4; 2 per thread)
        #pragma unroll
        for (int it = 0; it < 2; ++it) {
            int fl  = tid + it * 256;
            int row = fl >> 2;
            int kq  = fl & 3;
            const float4 v = *(const float4*)(x + (size_t)(m0 + row) * INP + k0 + kq * 4);
            As2[kq * 2    ][row] = make_float2(v.x, v.y);
            As2[kq * 2 + 1][row] = make_float2(v.z, v.w);
        }
        // load B tile: 64 rows x 16 k  (256 float4; 1 per thread)
        {
            int row = tid >> 2;
            int kq  = tid & 3;
            const float4 v = *(const float4*)(Wih + (size_t)(n0 + row) * INP + k0 + kq * 4);
            Bs2[kq * 2    ][row] = make_float2(v.x, v.y);
            Bs2[kq * 2 + 1][row] = make_float2(v.z, v.w);
        }
        __syncthreads();

        #pragma unroll
        for (int kk = 0; kk < 8; ++kk) {
            unsigned long long a[8], b[4];
            #pragma unroll
            for (int i = 0; i < 4; ++i) {
                ulonglong2 t2 = *(const ulonglong2*)&As2[kk][ty * 8 + i * 2];
                a[i * 2] = t2.x; a[i * 2 + 1] = t2.y;
            }
            #pragma unroll
            for (int j = 0; j < 2; ++j) {
                ulonglong2 t2 = *(const ulonglong2*)&Bs2[kk][tx * 4 + j * 2];
                b[j * 2] = t2.x; b[j * 2 + 1] = t2.y;
            }
            #pragma unroll
            for (int i = 0; i < 8; ++i)
                #pragma unroll
                for (int j = 0; j < 4; ++j)
                    ffma2(acc[i][j], a[i], b[j]);
        }
        __syncthreads();
    }

    // epilogue: add bias, scatter to g_xg[t][b][n]
    const int nb = n0 + tx * 4;
    float bj[4];
    #pragma unroll
    for (int j = 0; j < 4; ++j) bj[j] = bih[nb + j] + bhh[nb + j];

    #pragma unroll
    for (int i = 0; i < 8; ++i) {
        int m  = m0 + ty * 8 + i;
        int bb = m >> 9;          // batch (T=512)
        int tt = m & 511;         // timestep
        float4 r;
        r.x = hsum2(acc[i][0]) + bj[0];
        r.y = hsum2(acc[i][1]) + bj[1];
        r.z = hsum2(acc[i][2]) + bj[2];
        r.w = hsum2(acc[i][3]) + bj[3];
        *(float4*)(g_xg + ((size_t)tt * BATCH + bb) * G4 + nb) = r;
    }
}

// =================================================================================
// Kernel 2: persistent recurrence. 128 blocks x 128 threads.
// Block = (b-half [32 batches], j-group [8 hidden units]); owns all 4 gates of its
// j's -> pointwise update is block-local; one grid barrier per timestep.
// W_hh slice cached in SMEM once; h staged into SMEM each step; c in registers.
// =================================================================================
__global__ __launch_bounds__(128) void lstm_rec_kernel(
        const float* __restrict__ h0, const float* __restrict__ c0,
        const float* __restrict__ Whh, float* __restrict__ out, int write_tail) {
    extern __shared__ __align__(16) float smem[];
    float* sw = smem;                    // 32 rows x HPAD  (W slice)
    float* sh = smem + 32 * HPAD;        // 32 rows x HPAD  (h slice)

    const int tid   = threadIdx.x;
    const int jg    = blockIdx.x & 63;
    const int bhalf = blockIdx.x >> 6;
    const int b_base = bhalf * 32;
    const int jj = tid & 7;              // hidden unit within group
    const int bg = tid >> 3;             // 0..15 (batch pair group)
    const int J  = jg * 8 + jj;          // global hidden index

    // one-time W_hh slice load: rows r = gate*8 + jj_local -> global row gate*HID + J
    #pragma unroll 8
    for (int q = tid; q < 32 * 128; q += 128) {
        int r  = q >> 7;
        int k4 = (q & 127) * 4;
        int gr = (r >> 3) * HID + jg * 8 + (r & 7);
        *(float4*)(sw + r * HPAD + k4) =
            __ldcg((const float4*)(Whh + (size_t)gr * HID + k4));
    }

    const int b0 = b_base + bg * 2;
    float cc[2];
    cc[0] = c0[(size_t)b0 * HID + J];
    cc[1] = c0[(size_t)(b0 + 1) * HID + J];

    const unsigned long long* wu[4];
    #pragma unroll
    for (int g = 0; g < 4; ++g)
        wu[g] = (const unsigned long long*)(sw + (g * 8 + jj) * HPAD);
    const unsigned long long* hu0 = (const unsigned long long*)(sh + (bg * 2) * HPAD);
    const unsigned long long* hu1 = (const unsigned long long*)(sh + (bg * 2 + 1) * HPAD);

    float* outH = out + (size_t)BATCH * T_STEPS * HID;
    float* outC = outH + BATCH * HID;

    for (int t = 0; t < T_STEPS; ++t) {
        const float* hsrc = (t == 0) ? h0 : g_hbuf[t & 1];
        // stage h slice (L2 reads; __ldcg avoids stale L1 from same-parity steps)
        #pragma unroll 8
        for (int q = tid; q < 32 * 128; q += 128) {
            int bb = q >> 7;
            int k4 = (q & 127) * 4;
            *(float4*)(sh + bb * HPAD + k4) =
                __ldcg((const float4*)(hsrc + (size_t)(b_base + bb) * HID + k4));
        }
        __syncthreads();

        // prefetch xg for this thread's 8 outputs
        float xr[4][2];
        {
            size_t xbase = ((size_t)t * BATCH + b0) * G4 + J;
            #pragma unroll
            for (int g = 0; g < 4; ++g) {
                xr[g][0] = g_xg[xbase + g * HID];
                xr[g][1] = g_xg[xbase + G4 + g * HID];
            }
        }

        unsigned long long aA[2][4], aB[2][4];
        #pragma unroll
        for (int bi = 0; bi < 2; ++bi)
            #pragma unroll
            for (int g = 0; g < 4; ++g) { aA[bi][g] = 0ull; aB[bi][g] = 0ull; }

        // dot over k: 4 k per iter, packed f32x2
        #pragma unroll 4
        for (int p = 0; p < 256; p += 2) {
            ulonglong2 hva = *(const ulonglong2*)(hu0 + p);
            ulonglong2 hvb = *(const ulonglong2*)(hu1 + p);
            #pragma unroll
            for (int g = 0; g < 4; ++g) {
                ulonglong2 wv = *(const ulonglong2*)(wu[g] + p);
                ffma2(aA[0][g], hva.x, wv.x);
                ffma2(aB[0][g], hva.y, wv.y);
                ffma2(aA[1][g], hvb.x, wv.x);
                ffma2(aB[1][g], hvb.y, wv.y);
            }
        }

        float* hdst = g_hbuf[(t + 1) & 1];
        #pragma unroll
        for (int bi = 0; bi < 2; ++bi) {
            float pi = hsum2(aA[bi][0]) + hsum2(aB[bi][0]) + xr[0][bi];
            float pf = hsum2(aA[bi][1]) + hsum2(aB[bi][1]) + xr[1][bi];
            float pg = hsum2(aA[bi][2]) + hsum2(aB[bi][2]) + xr[2][bi];
            float po = hsum2(aA[bi][3]) + hsum2(aB[bi][3]) + xr[3][bi];
            float ii = 1.f / (1.f + __expf(-pi));
            float ff = 1.f / (1.f + __expf(-pf));
            float gg = tanhf(pg);
            float oo = 1.f / (1.f + __expf(-po));
            float c  = ff * cc[bi] + ii * gg;
            cc[bi]   = c;
            float h  = oo * tanhf(c);
            int b    = b0 + bi;
            hdst[(size_t)b * HID + J] = h;
            out[((size_t)b * T_STEPS + t) * HID + J] = h;
            if (write_tail && t == T_STEPS - 1) {
                outH[(size_t)b * HID + J] = h;
                outC[(size_t)b * HID + J] = c;
            }
        }

        // ---- grid barrier (all 128 blocks co-resident) ----
        __threadfence();
        __syncthreads();
        if (tid == 0) {
            atomicAdd(&g_bar, 1u);
            unsigned target = (unsigned)(t + 1) * NBLK;
            while (*((volatile unsigned*)&g_bar) < target) { }
            __threadfence();
        }
        __syncthreads();
    }
}

// =================================================================================
extern "C" void kernel_launch(void* const* d_in, const int* in_sizes, int n_in,
                              void* d_out, int out_size) {
    const float* x   = (const float*)d_in[0];
    const float* h0  = (const float*)d_in[1];
    const float* c0  = (const float*)d_in[2];
    const float* Wih = (const float*)d_in[3];
    const float* Whh = (const float*)d_in[4];
    const float* bih = (const float*)d_in[5];
    const float* bhh = (const float*)d_in[6];
    float* out = (float*)d_out;

    const size_t total_elems = (size_t)BATCH * T_STEPS * HID + 2 * (size_t)BATCH * HID;
    const int write_tail = ((size_t)out_size >= total_elems) ? 1 : 0;

    const int rec_smem = 2 * 32 * HPAD * (int)sizeof(float);  // 132096 B
    cudaFuncSetAttribute(lstm_rec_kernel, cudaFuncAttributeMaxDynamicSharedMemorySize,
                         rec_smem);

    // reset grid-barrier counter (captured as a memset node; runs every replay)
    void* barAddr = nullptr;
    cudaGetSymbolAddress(&barAddr, g_bar);
    cudaMemsetAsync(barAddr, 0, sizeof(unsigned int));

    dim3 g1(G4 / 64, (BATCH * T_STEPS) / 128);
    xg_gemm_kernel<<<g1, 256>>>(x, Wih, bih, bhh);
    lstm_rec_kernel<<<NBLK, 128, rec_smem>>>(h0, c0, Whh, out, write_tail);
}

// round 2
// speedup vs baseline: 1.0807x; 1.0807x over previous
#include <cuda_runtime.h>
#include <cstdint>
#include <cstddef>

#define T_STEPS 512
#define BATCH   64
#define HID     512
#define INP     512
#define G4      2048            // 4*HID
#define HPAD    516             // padded row stride (floats) to break bank conflicts
#define NBLK    128             // persistent grid size

// ---------------- device scratch (static; no runtime allocation) ----------------
__device__ float g_xg[(size_t)T_STEPS * BATCH * G4];   // [T][B][4H]  (256 MB)
__device__ float g_hbuf[2][BATCH * HID];               // ping-pong h
__device__ unsigned int g_bar;                         // grid barrier counter

// ---------------- f32x2 helpers ----------------
__device__ __forceinline__ void ffma2(unsigned long long &c, unsigned long long a,
                                      unsigned long long b) {
    asm("fma.rn.f32x2 %0, %1, %2, %0;" : "+l"(c) : "l"(a), "l"(b));
}
__device__ __forceinline__ float hsum2(unsigned long long v) {
    float lo, hi;
    asm("mov.b64 {%0, %1}, %2;" : "=f"(lo), "=f"(hi) : "l"(v));
    return lo + hi;
}

// =================================================================================
// Kernel 1: xg[t][b][g] = x[b,t,:] . W_ih[g,:] + (b_ih[g] + b_hh[g])
// GEMM M=32768 (m = b*512+t), N=2048, K=512.  Tile 128x64, 256 threads, thread 8x4.
// =================================================================================
__global__ __launch_bounds__(256) void xg_gemm_kernel(
        const float* __restrict__ x, const float* __restrict__ Wih,
        const float* __restrict__ bih, const float* __restrict__ bhh) {
    __shared__ __align__(16) float2 As2[8][128];   // [k_pair][m]
    __shared__ __align__(16) float2 Bs2[8][64];    // [k_pair][n]

    const int tid = threadIdx.x;
    const int tx = tid & 15;        // n-dim thread coord (0..15)
    const int ty = tid >> 4;        // m-dim thread coord (0..15)
    const int m0 = blockIdx.y * 128;
    const int n0 = blockIdx.x * 64;

    unsigned long long acc[8][4];
    #pragma unroll
    for (int i = 0; i < 8; ++i)
        #pragma unroll
        for (int j = 0; j < 4; ++j) acc[i][j] = 0ull;

    for (int k0 = 0; k0 < INP; k0 += 16) {
        #pragma unroll
        for (int it = 0; it < 2; ++it) {
            int fl  = tid + it * 256;
            int row = fl >> 2;
            int kq  = fl & 3;
            const float4 v = *(const float4*)(x + (size_t)(m0 + row) * INP + k0 + kq * 4);
            As2[kq * 2    ][row] = make_float2(v.x, v.y);
            As2[kq * 2 + 1][row] = make_float2(v.z, v.w);
        }
        {
            int row = tid >> 2;
            int kq  = tid & 3;
            const float4 v = *(const float4*)(Wih + (size_t)(n0 + row) * INP + k0 + kq * 4);
            Bs2[kq * 2    ][row] = make_float2(v.x, v.y);
            Bs2[kq * 2 + 1][row] = make_float2(v.z, v.w);
        }
        __syncthreads();

        #pragma unroll
        for (int kk = 0; kk < 8; ++kk) {
            unsigned long long a[8], b[4];
            #pragma unroll
            for (int i = 0; i < 4; ++i) {
                ulonglong2 t2 = *(const ulonglong2*)&As2[kk][ty * 8 + i * 2];
                a[i * 2] = t2.x; a[i * 2 + 1] = t2.y;
            }
            #pragma unroll
            for (int j = 0; j < 2; ++j) {
                ulonglong2 t2 = *(const ulonglong2*)&Bs2[kk][tx * 4 + j * 2];
                b[j * 2] = t2.x; b[j * 2 + 1] = t2.y;
            }
            #pragma unroll
            for (int i = 0; i < 8; ++i)
                #pragma unroll
                for (int j = 0; j < 4; ++j)
                    ffma2(acc[i][j], a[i], b[j]);
        }
        __syncthreads();
    }

    const int nb = n0 + tx * 4;
    float bj[4];
    #pragma unroll
    for (int j = 0; j < 4; ++j) bj[j] = bih[nb + j] + bhh[nb + j];

    #pragma unroll
    for (int i = 0; i < 8; ++i) {
        int m  = m0 + ty * 8 + i;
        int bb = m >> 9;          // batch (T=512)
        int tt = m & 511;         // timestep
        float4 r;
        r.x = hsum2(acc[i][0]) + bj[0];
        r.y = hsum2(acc[i][1]) + bj[1];
        r.z = hsum2(acc[i][2]) + bj[2];
        r.w = hsum2(acc[i][3]) + bj[3];
        *(float4*)(g_xg + ((size_t)tt * BATCH + bb) * G4 + nb) = r;
    }
}

// =================================================================================
// Kernel 2: persistent recurrence. 128 blocks x 256 threads (2 warps/SMSP).
// Thread layout: tidL = tid&127 -> jj (8 J), bg (16 batch pairs); kh = tid>>7
// splits K in half (k in [kh*256, kh*256+256)). After the dot loop, kh=1 writes
// partials to SMEM and kh=0 reduces + does the pointwise gate update.
// W_hh slice cached in SMEM once; h staged each step; c in registers (kh=0).
// =================================================================================
__global__ __launch_bounds__(256) void lstm_rec_kernel(
        const float* __restrict__ h0, const float* __restrict__ c0,
        const float* __restrict__ Whh, float* __restrict__ out, int write_tail) {
    extern __shared__ __align__(16) float smem[];
    float* sw = smem;                    // 32 rows x HPAD  (W slice)
    float* sh = smem + 32 * HPAD;        // 32 rows x HPAD  (h slice, also red scratch)

    const int tid   = threadIdx.x;
    const int tidL  = tid & 127;
    const int kh    = tid >> 7;          // K-half: 0 or 1
    const int jg    = blockIdx.x & 63;
    const int bhalf = blockIdx.x >> 6;
    const int b_base = bhalf * 32;
    const int jj = tidL & 7;             // hidden unit within group
    const int bg = tidL >> 3;            // 0..15 (batch pair group)
    const int J  = jg * 8 + jj;          // global hidden index

    // one-time W_hh slice load: rows r = gate*8 + jj_local -> global row gate*HID + J
    #pragma unroll 8
    for (int q = tid; q < 32 * 128; q += 256) {
        int r  = q >> 7;
        int k4 = (q & 127) * 4;
        int gr = (r >> 3) * HID + jg * 8 + (r & 7);
        *(float4*)(sw + r * HPAD + k4) =
            __ldcg((const float4*)(Whh + (size_t)gr * HID + k4));
    }

    const int b0 = b_base + bg * 2;
    float cc[2] = {0.f, 0.f};
    if (kh == 0) {
        cc[0] = c0[(size_t)b0 * HID + J];
        cc[1] = c0[(size_t)(b0 + 1) * HID + J];
    }

    const int pbase = kh * 128;          // u64 offset of this warp's K-half
    const unsigned long long* wu[4];
    #pragma unroll
    for (int g = 0; g < 4; ++g)
        wu[g] = (const unsigned long long*)(sw + (g * 8 + jj) * HPAD) + pbase;
    const unsigned long long* hu0 =
        (const unsigned long long*)(sh + (bg * 2) * HPAD) + pbase;
    const unsigned long long* hu1 =
        (const unsigned long long*)(sh + (bg * 2 + 1) * HPAD) + pbase;

    float* outH = out + (size_t)BATCH * T_STEPS * HID;
    float* outC = outH + BATCH * HID;

    for (int t = 0; t < T_STEPS; ++t) {
        const float* hsrc = (t == 0) ? h0 : g_hbuf[t & 1];
        // stage h slice (L2 reads; __ldcg avoids stale L1)
        #pragma unroll 8
        for (int q = tid; q < 32 * 128; q += 256) {
            int bb = q >> 7;
            int k4 = (q & 127) * 4;
            *(float4*)(sh + bb * HPAD + k4) =
                __ldcg((const float4*)(hsrc + (size_t)(b_base + bb) * HID + k4));
        }
        __syncthreads();

        // prefetch xg for this thread's 8 outputs (kh=0 warps only; uniform per warp)
        float xr[4][2];
        if (kh == 0) {
            size_t xbase = ((size_t)t * BATCH + b0) * G4 + J;
            #pragma unroll
            for (int g = 0; g < 4; ++g) {
                xr[g][0] = g_xg[xbase + g * HID];
                xr[g][1] = g_xg[xbase + G4 + g * HID];
            }
        }

        unsigned long long aA[2][4], aB[2][4];
        #pragma unroll
        for (int bi = 0; bi < 2; ++bi)
            #pragma unroll
            for (int g = 0; g < 4; ++g) { aA[bi][g] = 0ull; aB[bi][g] = 0ull; }

        // dot over this warp's K-half: 4 k per iter, packed f32x2
        #pragma unroll 8
        for (int p = 0; p < 128; p += 2) {
            ulonglong2 hva = *(const ulonglong2*)(hu0 + p);
            ulonglong2 hvb = *(const ulonglong2*)(hu1 + p);
            #pragma unroll
            for (int g = 0; g < 4; ++g) {
                ulonglong2 wv = *(const ulonglong2*)(wu[g] + p);
                ffma2(aA[0][g], hva.x, wv.x);
                ffma2(aB[0][g], hva.y, wv.y);
                ffma2(aA[1][g], hvb.x, wv.x);
                ffma2(aB[1][g], hvb.y, wv.y);
            }
        }

        // combine halves of each accumulator into one float per output
        float part[2][4];
        #pragma unroll
        for (int bi = 0; bi < 2; ++bi)
            #pragma unroll
            for (int g = 0; g < 4; ++g)
                part[bi][g] = hsum2(aA[bi][g]) + hsum2(aB[bi][g]);

        // cross-warp (K-half) reduction through SMEM scratch (reuse sh region)
        __syncthreads();                 // dot loop done reading sh
        float* red = sh;                 // 128 threads x 8 floats
        if (kh == 1) {
            float4* dst = (float4*)(red + tidL * 8);
            dst[0] = make_float4(part[0][0], part[0][1], part[0][2], part[0][3]);
            dst[1] = make_float4(part[1][0], part[1][1], part[1][2], part[1][3]);
        }
        __syncthreads();

        if (kh == 0) {
            const float4* src = (const float4*)(red + tidL * 8);
            float4 r0 = src[0], r1 = src[1];
            part[0][0] += r0.x; part[0][1] += r0.y; part[0][2] += r0.z; part[0][3] += r0.w;
            part[1][0] += r1.x; part[1][1] += r1.y; part[1][2] += r1.z; part[1][3] += r1.w;

            float* hdst = g_hbuf[(t + 1) & 1];
            #pragma unroll
            for (int bi = 0; bi < 2; ++bi) {
                float pi = part[bi][0] + xr[0][bi];
                float pf = part[bi][1] + xr[1][bi];
                float pg = part[bi][2] + xr[2][bi];
                float po = part[bi][3] + xr[3][bi];
                float ii = 1.f / (1.f + __expf(-pi));
                float ff = 1.f / (1.f + __expf(-pf));
                float gg = tanhf(pg);
                float oo = 1.f / (1.f + __expf(-po));
                float c  = ff * cc[bi] + ii * gg;
                cc[bi]   = c;
                float h  = oo * tanhf(c);
                int b    = b0 + bi;
                hdst[(size_t)b * HID + J] = h;
                out[((size_t)b * T_STEPS + t) * HID + J] = h;
                if (write_tail && t == T_STEPS - 1) {
                    outH[(size_t)b * HID + J] = h;
                    outC[(size_t)b * HID + J] = c;
                }
            }
            __threadfence();             // make h stores visible before barrier signal
        }

        // ---- grid barrier (all 128 blocks co-resident) ----
        __syncthreads();
        if (tid == 0) {
            atomicAdd(&g_bar, 1u);
            unsigned target = (unsigned)(t + 1) * NBLK;
            while (*((volatile unsigned*)&g_bar) < target) { }
            __threadfence();
        }
        __syncthreads();
    }
}

// =================================================================================
extern "C" void kernel_launch(void* const* d_in, const int* in_sizes, int n_in,
                              void* d_out, int out_size) {
    const float* x   = (const float*)d_in[0];
    const float* h0  = (const float*)d_in[1];
    const float* c0  = (const float*)d_in[2];
    const float* Wih = (const float*)d_in[3];
    const float* Whh = (const float*)d_in[4];
    const float* bih = (const float*)d_in[5];
    const float* bhh = (const float*)d_in[6];
    float* out = (float*)d_out;

    const size_t total_elems = (size_t)BATCH * T_STEPS * HID + 2 * (size_t)BATCH * HID;
    const int write_tail = ((size_t)out_size >= total_elems) ? 1 : 0;

    const int rec_smem = 2 * 32 * HPAD * (int)sizeof(float);  // 132096 B
    cudaFuncSetAttribute(lstm_rec_kernel, cudaFuncAttributeMaxDynamicSharedMemorySize,
                         rec_smem);

    // reset grid-barrier counter (captured as a memset node; runs every replay)
    void* barAddr = nullptr;
    cudaGetSymbolAddress(&barAddr, g_bar);
    cudaMemsetAsync(barAddr, 0, sizeof(unsigned int));

    dim3 g1(G4 / 64, (BATCH * T_STEPS) / 128);
    xg_gemm_kernel<<<g1, 256>>>(x, Wih, bih, bhh);
    lstm_rec_kernel<<<NBLK, 256, rec_smem>>>(h0, c0, Whh, out, write_tail);
}